// round 2
// baseline (speedup 1.0000x reference)
#include <cuda_runtime.h>
#include <math.h>

#define NMAX 1000
#define DFLAT 25088   // 7*7*512
#define HID 4096
#define NHEAD 101     // 21 cls + 80 reg

__device__ float g_pooled[NMAX * DFLAT];   // ~100 MB
__device__ float g_h1[NMAX * HID];
__device__ float g_h2[NMAX * HID];
__device__ float g_WT[NHEAD * HID];        // transposed head weights [j][k]

// ---------------------------------------------------------------------------
// Kernel 1: crop_and_resize (TF semantics, 14x14) + 2x2 maxpool -> pooled row
// One block per ROI. feats: [38,50,512] fp32 (L2-resident, 3.9 MB).
// ---------------------------------------------------------------------------
__global__ void roi_kernel(const float* __restrict__ feats,
                           const float* __restrict__ boxes, int N)
{
    int roi = blockIdx.x;
    if (roi >= N) return;
    __shared__ int   sy0[14], sy1[14], sx0[14], sx1[14];
    __shared__ float swy[14], swx[14];
    int t = threadIdx.x;
    if (t < 14) {
        float y1 = boxes[roi * 4 + 0];
        float x1 = boxes[roi * 4 + 1];
        float y2 = boxes[roi * 4 + 2];
        float x2 = boxes[roi * 4 + 3];
        float ys = y1 * 37.0f + (float)t * ((y2 - y1) * 37.0f / 13.0f);
        float xs = x1 * 49.0f + (float)t * ((x2 - x1) * 49.0f / 13.0f);
        float y0f = floorf(ys), x0f = floorf(xs);
        swy[t] = ys - y0f;
        swx[t] = xs - x0f;
        int y0 = min(max((int)y0f, 0), 37);
        int x0 = min(max((int)x0f, 0), 49);
        sy0[t] = y0; sy1[t] = min(y0 + 1, 37);
        sx0[t] = x0; sx1[t] = min(x0 + 1, 49);
    }
    __syncthreads();

    float* out = g_pooled + (size_t)roi * DFLAT;
    // 7*7 pooled positions * 128 float4 channel-chunks
    for (int idx = t; idx < 7 * 7 * 128; idx += blockDim.x) {
        int c4 = idx & 127;
        int p  = idx >> 7;      // 0..48
        int pr = p / 7, pc = p % 7;
        int c  = c4 * 4;
        float4 best = make_float4(-1e30f, -1e30f, -1e30f, -1e30f);
#pragma unroll
        for (int dy = 0; dy < 2; dy++) {
            int iy = 2 * pr + dy;
            int ay = sy0[iy], by = sy1[iy];
            float fy = swy[iy];
#pragma unroll
            for (int dx = 0; dx < 2; dx++) {
                int ix = 2 * pc + dx;
                int ax = sx0[ix], bx = sx1[ix];
                float fx = swx[ix];
                float4 v00 = *(const float4*)(feats + ((ay * 50 + ax) * 512 + c));
                float4 v01 = *(const float4*)(feats + ((ay * 50 + bx) * 512 + c));
                float4 v10 = *(const float4*)(feats + ((by * 50 + ax) * 512 + c));
                float4 v11 = *(const float4*)(feats + ((by * 50 + bx) * 512 + c));
                float4 top, bot, val;
                top.x = v00.x + fx * (v01.x - v00.x);
                top.y = v00.y + fx * (v01.y - v00.y);
                top.z = v00.z + fx * (v01.z - v00.z);
                top.w = v00.w + fx * (v01.w - v00.w);
                bot.x = v10.x + fx * (v11.x - v10.x);
                bot.y = v10.y + fx * (v11.y - v10.y);
                bot.z = v10.z + fx * (v11.z - v10.z);
                bot.w = v10.w + fx * (v11.w - v10.w);
                val.x = top.x + fy * (bot.x - top.x);
                val.y = top.y + fy * (bot.y - top.y);
                val.z = top.z + fy * (bot.z - top.z);
                val.w = top.w + fy * (bot.w - top.w);
                best.x = fmaxf(best.x, val.x);
                best.y = fmaxf(best.y, val.y);
                best.z = fmaxf(best.z, val.z);
                best.w = fmaxf(best.w, val.w);
            }
        }
        *(float4*)(out + (size_t)p * 512 + c) = best;
    }
}

// ---------------------------------------------------------------------------
// Kernel 2: tiled fp32 GEMM C[M,N] = relu?(A[M,K] @ B[K,N] + bias[N])
// 128x128 block tile, BK=8, 256 threads, 8x8 register tile per thread.
// Requires K % 8 == 0, N % 4 == 0 (true: K in {25088,4096}, N=4096).
// ---------------------------------------------------------------------------
#define BM 128
#define BN 128
#define BK 8
__global__ void __launch_bounds__(256, 2)
gemm_bias_act(const float* __restrict__ A, const float* __restrict__ B,
              const float* __restrict__ bias, float* __restrict__ C,
              int M, int N, int K, int relu)
{
    __shared__ float As[BK][BM];
    __shared__ float Bs[BK][BN];
    int tid = threadIdx.x;
    int bm = blockIdx.y * BM;
    int bn = blockIdx.x * BN;

    int arow = tid >> 1;          // 0..127
    int acol = (tid & 1) * 4;     // 0 or 4
    int brow = tid >> 5;          // 0..7
    int bcol = (tid & 31) * 4;    // 0..124
    int ty = tid >> 4, tx = tid & 15;

    float acc[8][8];
#pragma unroll
    for (int i = 0; i < 8; i++)
#pragma unroll
        for (int j = 0; j < 8; j++) acc[i][j] = 0.0f;

    bool a_ok = (bm + arow) < M;
    const float* aptr = A + (size_t)(bm + arow) * K + acol;
    const float* bptr = B + (size_t)brow * N + bn + bcol;

    for (int k0 = 0; k0 < K; k0 += BK) {
        float4 av = make_float4(0.f, 0.f, 0.f, 0.f);
        if (a_ok) av = *(const float4*)(aptr + k0);
        As[acol + 0][arow] = av.x;
        As[acol + 1][arow] = av.y;
        As[acol + 2][arow] = av.z;
        As[acol + 3][arow] = av.w;
        float4 bv = *(const float4*)(bptr + (size_t)k0 * N);
        *(float4*)&Bs[brow][bcol] = bv;
        __syncthreads();
#pragma unroll
        for (int k = 0; k < BK; k++) {
            float a[8], b[8];
#pragma unroll
            for (int i = 0; i < 8; i++) a[i] = As[k][ty * 8 + i];
#pragma unroll
            for (int j = 0; j < 8; j++) b[j] = Bs[k][tx * 8 + j];
#pragma unroll
            for (int i = 0; i < 8; i++)
#pragma unroll
                for (int j = 0; j < 8; j++) acc[i][j] += a[i] * b[j];
        }
        __syncthreads();
    }

#pragma unroll
    for (int i = 0; i < 8; i++) {
        int m = bm + ty * 8 + i;
        if (m >= M) break;
#pragma unroll
        for (int j = 0; j < 8; j++) {
            int n = bn + tx * 8 + j;
            float v = acc[i][j] + bias[n];
            if (relu) v = fmaxf(v, 0.0f);
            C[(size_t)m * N + n] = v;
        }
    }
}

// ---------------------------------------------------------------------------
// Kernel 3: transpose head weights into g_WT[j][k]  (j<21 -> Wc, else Wr)
// ---------------------------------------------------------------------------
__global__ void wt_kernel(const float* __restrict__ Wc, const float* __restrict__ Wr)
{
    for (int idx = blockIdx.x * blockDim.x + threadIdx.x; idx < NHEAD * HID;
         idx += gridDim.x * blockDim.x) {
        int j = idx >> 12;       // /4096
        int k = idx & 4095;
        g_WT[idx] = (j < 21) ? Wc[k * 21 + j] : Wr[k * 80 + (j - 21)];
    }
}

// ---------------------------------------------------------------------------
// Kernel 4: heads — 2 ROIs per block, warp-per-output dot products,
// softmax over 21 cls logits, write [cls | reg] into d_out.
// ---------------------------------------------------------------------------
#define RPB 2
__global__ void __launch_bounds__(256)
head_kernel(const float* __restrict__ bc, const float* __restrict__ br,
            float* __restrict__ out, int N)
{
    __shared__ float xs[RPB][HID];
    __shared__ float lg[RPB][NHEAD];
    int roi0 = blockIdx.x * RPB;
    int t = threadIdx.x;

    for (int r = 0; r < RPB; r++) {
        int roi = roi0 + r;
        if (roi < N) {
            const float4* src = (const float4*)(g_h2 + (size_t)roi * HID);
            for (int i = t; i < HID / 4; i += 256) ((float4*)xs[r])[i] = src[i];
        } else {
            for (int i = t; i < HID / 4; i += 256)
                ((float4*)xs[r])[i] = make_float4(0.f, 0.f, 0.f, 0.f);
        }
    }
    __syncthreads();

    int w = t >> 5, lane = t & 31;
    for (int j = w; j < NHEAD; j += 8) {
        const float4* wp = (const float4*)(g_WT + (size_t)j * HID);
        float acc0 = 0.f, acc1 = 0.f;
        for (int i = lane; i < HID / 4; i += 32) {
            float4 wv = wp[i];
            float4 a = ((float4*)xs[0])[i];
            float4 b = ((float4*)xs[1])[i];
            acc0 += wv.x * a.x + wv.y * a.y + wv.z * a.z + wv.w * a.w;
            acc1 += wv.x * b.x + wv.y * b.y + wv.z * b.z + wv.w * b.w;
        }
#pragma unroll
        for (int o = 16; o; o >>= 1) {
            acc0 += __shfl_down_sync(0xffffffffu, acc0, o);
            acc1 += __shfl_down_sync(0xffffffffu, acc1, o);
        }
        if (lane == 0) {
            float bias = (j < 21) ? bc[j] : br[j - 21];
            lg[0][j] = acc0 + bias;
            lg[1][j] = acc1 + bias;
        }
    }
    __syncthreads();

    // softmax for cls (21 values), one thread per roi (trivial work)
    if (t < RPB) {
        int roi = roi0 + t;
        if (roi < N) {
            float m = -1e30f;
            for (int j = 0; j < 21; j++) m = fmaxf(m, lg[t][j]);
            float s = 0.f;
            float e[21];
            for (int j = 0; j < 21; j++) { e[j] = expf(lg[t][j] - m); s += e[j]; }
            float inv = 1.0f / s;
            for (int j = 0; j < 21; j++) out[(size_t)roi * 21 + j] = e[j] * inv;
        }
    }
    // reg outputs
    for (int idx = t; idx < RPB * 80; idx += 256) {
        int r = idx / 80, j = idx % 80;
        int roi = roi0 + r;
        if (roi < N) out[(size_t)N * 21 + (size_t)roi * 80 + j] = lg[r][21 + j];
    }
}

// ---------------------------------------------------------------------------
extern "C" void kernel_launch(void* const* d_in, const int* in_sizes, int n_in,
                              void* d_out, int out_size)
{
    const float* feats = (const float*)d_in[0];
    const float* props = (const float*)d_in[1];
    const float* W1    = (const float*)d_in[2];
    const float* b1    = (const float*)d_in[3];
    const float* W2    = (const float*)d_in[4];
    const float* b2    = (const float*)d_in[5];
    const float* Wc    = (const float*)d_in[6];
    const float* bc    = (const float*)d_in[7];
    const float* Wr    = (const float*)d_in[8];
    const float* br    = (const float*)d_in[9];
    float* out = (float*)d_out;

    int N = in_sizes[1] / 4;
    if (N > NMAX) N = NMAX;

    float *pooled, *h1, *h2;
    cudaGetSymbolAddress((void**)&pooled, g_pooled);
    cudaGetSymbolAddress((void**)&h1, g_h1);
    cudaGetSymbolAddress((void**)&h2, g_h2);

    roi_kernel<<<N, 256>>>(feats, props, N);

    dim3 g1(HID / BN, (N + BM - 1) / BM);
    gemm_bias_act<<<g1, 256>>>(pooled, W1, b1, h1, N, HID, DFLAT, 1);
    gemm_bias_act<<<g1, 256>>>(h1, W2, b2, h2, N, HID, HID, 1);

    wt_kernel<<<256, 256>>>(Wc, Wr);
    head_kernel<<<(N + RPB - 1) / RPB, 256>>>(bc, br, out, N);
}

// round 9
// speedup vs baseline: 4.2184x; 4.2184x over previous
#include <cuda_runtime.h>
#include <cuda_bf16.h>
#include <math.h>
#include <stdint.h>

#define NMAX  1024
#define DFLAT 25088   // 7*7*512
#define HID   4096
#define NHEAD 101     // 21 cls + 80 reg

// ---------------- device scratch (static) ----------------
__device__ __nv_bfloat16 g_pool_hi[(size_t)NMAX * DFLAT];
__device__ __nv_bfloat16 g_pool_lo[(size_t)NMAX * DFLAT];
__device__ __nv_bfloat16 g_W1T_hi[(size_t)HID * DFLAT];
__device__ __nv_bfloat16 g_W1T_lo[(size_t)HID * DFLAT];
__device__ __nv_bfloat16 g_W2T_hi[(size_t)HID * HID];
__device__ __nv_bfloat16 g_W2T_lo[(size_t)HID * HID];
__device__ __nv_bfloat16 g_h1_hi[(size_t)NMAX * HID];
__device__ __nv_bfloat16 g_h1_lo[(size_t)NMAX * HID];
__device__ float g_h2[(size_t)NMAX * HID];
__device__ float g_WT[NHEAD * HID];

// ---------------- helpers ----------------
__device__ __forceinline__ uint32_t smem_u32(const void* p) {
    uint32_t a;
    asm("{ .reg .u64 t; cvta.to.shared.u64 t, %1; cvt.u32.u64 %0, t; }" : "=r"(a) : "l"(p));
    return a;
}
__device__ __forceinline__ uint32_t pack_bf(float a, float b) {
    return ((uint32_t)__bfloat16_as_ushort(__float2bfloat16(b)) << 16)
         |  (uint32_t)__bfloat16_as_ushort(__float2bfloat16(a));
}
__device__ __forceinline__ float bfres(float a) {
    return a - __bfloat162float(__float2bfloat16(a));
}

__device__ __forceinline__ void cp16(uint32_t dst, const void* src) {
    asm volatile("cp.async.cg.shared.global [%0], [%1], 16;" :: "r"(dst), "l"(src));
}
#define CP_COMMIT() asm volatile("cp.async.commit_group;" ::: "memory")
#define CP_WAIT(n)  asm volatile("cp.async.wait_group %0;" :: "n"(n) : "memory")

__device__ __forceinline__ void ldsm_x4(uint32_t tbase, int row0, int kbyte,
                                        int lane, uint32_t r[4]) {
    int sub = lane >> 3, rr = lane & 7;
    uint32_t off = (uint32_t)((row0 + ((sub & 1) << 3) + rr) * 128
                              + kbyte + ((sub >> 1) << 4));
    off ^= (off >> 3) & 0x70;   // SW128
    asm volatile("ldmatrix.sync.aligned.m8n8.x4.shared.b16 {%0,%1,%2,%3}, [%4];"
        : "=r"(r[0]), "=r"(r[1]), "=r"(r[2]), "=r"(r[3]) : "r"(tbase + off));
}

__device__ __forceinline__ void mma16816(float* c, const uint32_t* a,
                                         uint32_t b0, uint32_t b1) {
    asm volatile("mma.sync.aligned.m16n8k16.row.col.f32.bf16.bf16.f32 "
        "{%0,%1,%2,%3}, {%4,%5,%6,%7}, {%8,%9}, {%0,%1,%2,%3};"
        : "+f"(c[0]), "+f"(c[1]), "+f"(c[2]), "+f"(c[3])
        : "r"(a[0]), "r"(a[1]), "r"(a[2]), "r"(a[3]), "r"(b0), "r"(b1));
}

// ---------------------------------------------------------------------------
// Kernel 1: crop_and_resize (TF semantics, 14x14) + 2x2 maxpool -> bf16 hi/lo
// ---------------------------------------------------------------------------
__global__ void roi_kernel(const float* __restrict__ feats,
                           const float* __restrict__ boxes, int N,
                           __nv_bfloat16* __restrict__ out_hi,
                           __nv_bfloat16* __restrict__ out_lo)
{
    int roi = blockIdx.x;
    if (roi >= N) return;
    __shared__ int   sy0[14], sy1[14], sx0[14], sx1[14];
    __shared__ float swy[14], swx[14];
    int t = threadIdx.x;
    if (t < 14) {
        float y1 = boxes[roi * 4 + 0];
        float x1 = boxes[roi * 4 + 1];
        float y2 = boxes[roi * 4 + 2];
        float x2 = boxes[roi * 4 + 3];
        float ys = y1 * 37.0f + (float)t * ((y2 - y1) * 37.0f / 13.0f);
        float xs = x1 * 49.0f + (float)t * ((x2 - x1) * 49.0f / 13.0f);
        float y0f = floorf(ys), x0f = floorf(xs);
        swy[t] = ys - y0f;
        swx[t] = xs - x0f;
        int y0 = min(max((int)y0f, 0), 37);
        int x0 = min(max((int)x0f, 0), 49);
        sy0[t] = y0; sy1[t] = min(y0 + 1, 37);
        sx0[t] = x0; sx1[t] = min(x0 + 1, 49);
    }
    __syncthreads();

    size_t rbase = (size_t)roi * DFLAT;
    for (int idx = t; idx < 7 * 7 * 128; idx += blockDim.x) {
        int c4 = idx & 127;
        int p  = idx >> 7;
        int pr = p / 7, pc = p % 7;
        int c  = c4 * 4;
        float4 best = make_float4(-1e30f, -1e30f, -1e30f, -1e30f);
#pragma unroll
        for (int dy = 0; dy < 2; dy++) {
            int iy = 2 * pr + dy;
            int ay = sy0[iy], by = sy1[iy];
            float fy = swy[iy];
#pragma unroll
            for (int dx = 0; dx < 2; dx++) {
                int ix = 2 * pc + dx;
                int ax = sx0[ix], bx = sx1[ix];
                float fx = swx[ix];
                float4 v00 = *(const float4*)(feats + ((ay * 50 + ax) * 512 + c));
                float4 v01 = *(const float4*)(feats + ((ay * 50 + bx) * 512 + c));
                float4 v10 = *(const float4*)(feats + ((by * 50 + ax) * 512 + c));
                float4 v11 = *(const float4*)(feats + ((by * 50 + bx) * 512 + c));
                float4 top, bot, val;
                top.x = v00.x + fx * (v01.x - v00.x);
                top.y = v00.y + fx * (v01.y - v00.y);
                top.z = v00.z + fx * (v01.z - v00.z);
                top.w = v00.w + fx * (v01.w - v00.w);
                bot.x = v10.x + fx * (v11.x - v10.x);
                bot.y = v10.y + fx * (v11.y - v10.y);
                bot.z = v10.z + fx * (v11.z - v10.z);
                bot.w = v10.w + fx * (v11.w - v10.w);
                val.x = top.x + fy * (bot.x - top.x);
                val.y = top.y + fy * (bot.y - top.y);
                val.z = top.z + fy * (bot.z - top.z);
                val.w = top.w + fy * (bot.w - top.w);
                best.x = fmaxf(best.x, val.x);
                best.y = fmaxf(best.y, val.y);
                best.z = fmaxf(best.z, val.z);
                best.w = fmaxf(best.w, val.w);
            }
        }
        size_t o = rbase + (size_t)p * 512 + c;
        uint2 hv, lv;
        hv.x = pack_bf(best.x, best.y);
        hv.y = pack_bf(best.z, best.w);
        lv.x = pack_bf(bfres(best.x), bfres(best.y));
        lv.y = pack_bf(bfres(best.z), bfres(best.w));
        *(uint2*)(out_hi + o) = hv;
        *(uint2*)(out_lo + o) = lv;
    }
}

// ---------------------------------------------------------------------------
// Kernel 2: transpose fp32 [K,N] -> bf16 hi/lo [N,K]
// ---------------------------------------------------------------------------
__global__ void transpose_split(const float* __restrict__ W,
                                __nv_bfloat16* __restrict__ hi,
                                __nv_bfloat16* __restrict__ lo, int K, int N)
{
    __shared__ float tile[32][33];
    int kb = blockIdx.y * 32, nb = blockIdx.x * 32;
    int tx = threadIdx.x, ty = threadIdx.y;
    for (int i = ty; i < 32; i += 8)
        tile[i][tx] = W[(size_t)(kb + i) * N + nb + tx];
    __syncthreads();
    for (int i = ty; i < 32; i += 8) {
        float v = tile[tx][i];
        __nv_bfloat16 h = __float2bfloat16(v);
        size_t o = (size_t)(nb + i) * K + kb + tx;
        hi[o] = h;
        lo[o] = __float2bfloat16(v - __bfloat162float(h));
    }
}

// ---------------------------------------------------------------------------
// Kernel 3: mma.sync split-bf16 GEMM.  C[M,4096] = relu(A[M,K] @ B^T + bias)
// A hi/lo [rows,K] bf16 K-major; B hi/lo [4096,K] bf16 K-major.
// CTA tile 128x128, BK=64, 8 warps (4Mx2N), warp tile 32x64.
// 3-stage cp.async pipeline, SW128 swizzled SMEM, ldmatrix + mma.m16n8k16.
// 3-term split: Ah*Bh + Ah*Bl + Al*Bh, fp32 accumulate.
// ---------------------------------------------------------------------------
#define GBM 128
#define GBN 128
#define GKC 64                  // bf16 elems per stage (128 bytes/row)
#define TILE_B 16384            // 128 rows * 128B
#define STG_B  (4 * TILE_B)     // Ah, Al, Bh, Bl
#define NSTAGE 3
#define GEMM_SMEM (NSTAGE * STG_B + 1024)

__global__ void __launch_bounds__(256, 1)
gemm_split(const __nv_bfloat16* __restrict__ Ahi, const __nv_bfloat16* __restrict__ Alo,
           const __nv_bfloat16* __restrict__ Bhi, const __nv_bfloat16* __restrict__ Blo,
           const float* __restrict__ bias,
           __nv_bfloat16* __restrict__ outHi, __nv_bfloat16* __restrict__ outLo,
           float* __restrict__ outF,
           int M, int K, int mode)
{
    extern __shared__ char dsm_raw[];
    char* dsm = (char*)(((uintptr_t)dsm_raw + 1023) & ~(uintptr_t)1023);
    uint32_t sbase = smem_u32(dsm);

    int tid = threadIdx.x;
    int wid = tid >> 5, lane = tid & 31;
    int bm = blockIdx.x * GBM, bn = blockIdx.y * GBN;
    int wm = (wid >> 1) * 32, wn = (wid & 1) * 64;

    // per-tile global base pointers (row-offset already applied)
    const __nv_bfloat16* gp[4];
    gp[0] = Ahi + (size_t)bm * K;
    gp[1] = Alo + (size_t)bm * K;
    gp[2] = Bhi + (size_t)bn * K;
    gp[3] = Blo + (size_t)bn * K;

    const int S = K / GKC;

    // ---- stage loader: 4096 x 16B chunks / 256 threads = 16 per thread ----
    auto load_stage = [&](int s) {
        int kbyte0 = s * (GKC * 2);
        uint32_t sb = sbase + (uint32_t)(s % NSTAGE) * STG_B;
#pragma unroll
        for (int i = 0; i < 16; i++) {
            int idx  = tid + i * 256;
            int tile = idx >> 10;
            int row  = (idx >> 3) & 127;
            int c    = idx & 7;
            const char* src = (const char*)(gp[tile] + (size_t)row * K)
                            + kbyte0 + c * 16;
            uint32_t off = (uint32_t)(row * 128 + c * 16);
            off ^= (off >> 3) & 0x70;
            cp16(sb + (uint32_t)tile * TILE_B + off, src);
        }
        CP_COMMIT();
    };

    float acc[2][8][4];
#pragma unroll
    for (int mi = 0; mi < 2; mi++)
#pragma unroll
        for (int ni = 0; ni < 8; ni++)
#pragma unroll
            for (int j = 0; j < 4; j++) acc[mi][ni][j] = 0.0f;

    load_stage(0);
    load_stage(1);

    for (int s = 0; s < S; s++) {
        if (s + 2 < S) load_stage(s + 2);
        if (s + 2 < S)      { CP_WAIT(2); }
        else if (s + 1 < S) { CP_WAIT(1); }
        else                { CP_WAIT(0); }
        __syncthreads();

        uint32_t sb  = sbase + (uint32_t)(s % NSTAGE) * STG_B;
        uint32_t tAh = sb, tAl = sb + TILE_B;
        uint32_t tBh = sb + 2 * TILE_B, tBl = sb + 3 * TILE_B;

#pragma unroll
        for (int ks = 0; ks < 4; ks++) {
            int kb = ks * 32;   // 16 bf16 = 32 bytes
            uint32_t a[2][2][4];
#pragma unroll
            for (int mi = 0; mi < 2; mi++) {
                ldsm_x4(tAh, wm + mi * 16, kb, lane, a[0][mi]);
                ldsm_x4(tAl, wm + mi * 16, kb, lane, a[1][mi]);
            }
            uint32_t b[4][4];
            // Bh: Ah*Bh and Al*Bh
#pragma unroll
            for (int g = 0; g < 4; g++) ldsm_x4(tBh, wn + g * 16, kb, lane, b[g]);
#pragma unroll
            for (int mi = 0; mi < 2; mi++)
#pragma unroll
                for (int g = 0; g < 4; g++) {
                    mma16816(acc[mi][2 * g],     a[0][mi], b[g][0], b[g][2]);
                    mma16816(acc[mi][2 * g + 1], a[0][mi], b[g][1], b[g][3]);
                    mma16816(acc[mi][2 * g],     a[1][mi], b[g][0], b[g][2]);
                    mma16816(acc[mi][2 * g + 1], a[1][mi], b[g][1], b[g][3]);
                }
            // Bl: Ah*Bl
#pragma unroll
            for (int g = 0; g < 4; g++) ldsm_x4(tBl, wn + g * 16, kb, lane, b[g]);
#pragma unroll
            for (int mi = 0; mi < 2; mi++)
#pragma unroll
                for (int g = 0; g < 4; g++) {
                    mma16816(acc[mi][2 * g],     a[0][mi], b[g][0], b[g][2]);
                    mma16816(acc[mi][2 * g + 1], a[0][mi], b[g][1], b[g][3]);
                }
        }
        __syncthreads();
    }

    // ---- epilogue ----
    int lq = lane >> 2, lr = lane & 3;
#pragma unroll
    for (int mi = 0; mi < 2; mi++) {
#pragma unroll
        for (int half = 0; half < 2; half++) {   // c0,c1 then c2,c3 (row +8)
            int m = bm + wm + mi * 16 + lq + half * 8;
            if (m >= M) continue;
#pragma unroll
            for (int ni = 0; ni < 8; ni++) {
                int n = bn + wn + ni * 8 + lr * 2;
                float2 bv = *(const float2*)(bias + n);
                float v0 = fmaxf(acc[mi][ni][2 * half]     + bv.x, 0.0f);
                float v1 = fmaxf(acc[mi][ni][2 * half + 1] + bv.y, 0.0f);
                if (mode == 0) {
                    *(uint32_t*)(outHi + (size_t)m * HID + n) = pack_bf(v0, v1);
                    *(uint32_t*)(outLo + (size_t)m * HID + n) =
                        pack_bf(bfres(v0), bfres(v1));
                } else {
                    float2 ov = make_float2(v0, v1);
                    *(float2*)(outF + (size_t)m * HID + n) = ov;
                }
            }
        }
    }
}

// ---------------------------------------------------------------------------
// Kernel 4: head weight transpose (tiny)
// ---------------------------------------------------------------------------
__global__ void wt_kernel(const float* __restrict__ Wc, const float* __restrict__ Wr)
{
    for (int idx = blockIdx.x * blockDim.x + threadIdx.x; idx < NHEAD * HID;
         idx += gridDim.x * blockDim.x) {
        int j = idx >> 12;
        int k = idx & 4095;
        g_WT[idx] = (j < 21) ? Wc[k * 21 + j] : Wr[k * 80 + (j - 21)];
    }
}

// ---------------------------------------------------------------------------
// Kernel 5: heads + softmax
// ---------------------------------------------------------------------------
#define RPB 2
__global__ void __launch_bounds__(256)
head_kernel(const float* __restrict__ bc, const float* __restrict__ br,
            float* __restrict__ out, int N)
{
    __shared__ float xs[RPB][HID];
    __shared__ float lg[RPB][NHEAD];
    int roi0 = blockIdx.x * RPB;
    int t = threadIdx.x;

    for (int r = 0; r < RPB; r++) {
        int roi = roi0 + r;
        if (roi < N) {
            const float4* src = (const float4*)(g_h2 + (size_t)roi * HID);
            for (int i = t; i < HID / 4; i += 256) ((float4*)xs[r])[i] = src[i];
        } else {
            for (int i = t; i < HID / 4; i += 256)
                ((float4*)xs[r])[i] = make_float4(0.f, 0.f, 0.f, 0.f);
        }
    }
    __syncthreads();

    int w = t >> 5, lane = t & 31;
    for (int j = w; j < NHEAD; j += 8) {
        const float4* wp = (const float4*)(g_WT + (size_t)j * HID);
        float acc0 = 0.f, acc1 = 0.f;
        for (int i = lane; i < HID / 4; i += 32) {
            float4 wv = wp[i];
            float4 a = ((float4*)xs[0])[i];
            float4 b = ((float4*)xs[1])[i];
            acc0 += wv.x * a.x + wv.y * a.y + wv.z * a.z + wv.w * a.w;
            acc1 += wv.x * b.x + wv.y * b.y + wv.z * b.z + wv.w * b.w;
        }
#pragma unroll
        for (int o = 16; o; o >>= 1) {
            acc0 += __shfl_down_sync(0xffffffffu, acc0, o);
            acc1 += __shfl_down_sync(0xffffffffu, acc1, o);
        }
        if (lane == 0) {
            float bias = (j < 21) ? bc[j] : br[j - 21];
            lg[0][j] = acc0 + bias;
            lg[1][j] = acc1 + bias;
        }
    }
    __syncthreads();

    if (t < RPB) {
        int roi = roi0 + t;
        if (roi < N) {
            float mx = -1e30f;
            for (int j = 0; j < 21; j++) mx = fmaxf(mx, lg[t][j]);
            float s = 0.f;
            float e[21];
            for (int j = 0; j < 21; j++) { e[j] = expf(lg[t][j] - mx); s += e[j]; }
            float inv = 1.0f / s;
            for (int j = 0; j < 21; j++) out[(size_t)roi * 21 + j] = e[j] * inv;
        }
    }
    for (int idx = t; idx < RPB * 80; idx += 256) {
        int r = idx / 80, j = idx % 80;
        int roi = roi0 + r;
        if (roi < N) out[(size_t)N * 21 + (size_t)roi * 80 + j] = lg[r][21 + j];
    }
}

// ---------------------------------------------------------------------------
extern "C" void kernel_launch(void* const* d_in, const int* in_sizes, int n_in,
                              void* d_out, int out_size)
{
    const float* feats = (const float*)d_in[0];
    const float* props = (const float*)d_in[1];
    const float* W1    = (const float*)d_in[2];
    const float* b1    = (const float*)d_in[3];
    const float* W2    = (const float*)d_in[4];
    const float* b2    = (const float*)d_in[5];
    const float* Wc    = (const float*)d_in[6];
    const float* bc    = (const float*)d_in[7];
    const float* Wr    = (const float*)d_in[8];
    const float* br    = (const float*)d_in[9];
    float* out = (float*)d_out;

    int N = in_sizes[1] / 4;
    if (N > 1000) N = 1000;

    __nv_bfloat16 *phi, *plo, *w1h, *w1l, *w2h, *w2l, *h1h, *h1l;
    cudaGetSymbolAddress((void**)&phi, g_pool_hi);
    cudaGetSymbolAddress((void**)&plo, g_pool_lo);
    cudaGetSymbolAddress((void**)&w1h, g_W1T_hi);
    cudaGetSymbolAddress((void**)&w1l, g_W1T_lo);
    cudaGetSymbolAddress((void**)&w2h, g_W2T_hi);
    cudaGetSymbolAddress((void**)&w2l, g_W2T_lo);
    cudaGetSymbolAddress((void**)&h1h, g_h1_hi);
    cudaGetSymbolAddress((void**)&h1l, g_h1_lo);
    float* h2;
    cudaGetSymbolAddress((void**)&h2, g_h2);

    cudaFuncSetAttribute(gemm_split,
                         cudaFuncAttributeMaxDynamicSharedMemorySize, GEMM_SMEM);

    // weight prep
    transpose_split<<<dim3(HID / 32, DFLAT / 32), dim3(32, 8)>>>(W1, w1h, w1l, DFLAT, HID);
    transpose_split<<<dim3(HID / 32, HID / 32),  dim3(32, 8)>>>(W2, w2h, w2l, HID, HID);
    wt_kernel<<<256, 256>>>(Wc, Wr);

    // ROI pooling -> bf16 hi/lo
    roi_kernel<<<N, 256>>>(feats, props, N, phi, plo);

    // blockIdx.x = M-tile so CTAs sharing a B strip are schedule-adjacent
    int MT = (N + GBM - 1) / GBM;
    dim3 grid(MT, HID / GBN);
    gemm_split<<<grid, 256, GEMM_SMEM>>>(phi, plo, w1h, w1l, b1,
                                         h1h, h1l, nullptr, N, DFLAT, 0);
    gemm_split<<<grid, 256, GEMM_SMEM>>>(h1h, h1l, w2h, w2l, b2,
                                         nullptr, nullptr, h2, N, HID, 1);

    head_kernel<<<(N + RPB - 1) / RPB, 256>>>(bc, br, out, N);
}

// round 12
// speedup vs baseline: 4.2865x; 1.0161x over previous
#include <cuda_runtime.h>
#include <cuda_bf16.h>
#include <math.h>
#include <stdint.h>

#define NMAX  1024
#define DFLAT 25088   // 7*7*512
#define HID   4096
#define NHEAD 101     // 21 cls + 80 reg

// ---------------- device scratch (static) ----------------
__device__ __nv_bfloat16 g_pool_hi[(size_t)NMAX * DFLAT];
__device__ __nv_bfloat16 g_pool_lo[(size_t)NMAX * DFLAT];
__device__ __nv_bfloat16 g_W1T_hi[(size_t)HID * DFLAT];
__device__ __nv_bfloat16 g_W1T_lo[(size_t)HID * DFLAT];
__device__ __nv_bfloat16 g_W2T_hi[(size_t)HID * HID];
__device__ __nv_bfloat16 g_W2T_lo[(size_t)HID * HID];
__device__ __nv_bfloat16 g_h1_hi[(size_t)NMAX * HID];
__device__ __nv_bfloat16 g_h1_lo[(size_t)NMAX * HID];
__device__ float g_h2[(size_t)NMAX * HID];
__device__ float g_WT[NHEAD * HID];

// ---------------- helpers ----------------
__device__ __forceinline__ uint32_t smem_u32(const void* p) {
    uint32_t a;
    asm("{ .reg .u64 t; cvta.to.shared.u64 t, %1; cvt.u32.u64 %0, t; }" : "=r"(a) : "l"(p));
    return a;
}
__device__ __forceinline__ uint32_t pack_bf(float a, float b) {
    return ((uint32_t)__bfloat16_as_ushort(__float2bfloat16(b)) << 16)
         |  (uint32_t)__bfloat16_as_ushort(__float2bfloat16(a));
}
__device__ __forceinline__ float bfres(float a) {
    return a - __bfloat162float(__float2bfloat16(a));
}

__device__ __forceinline__ void cp16(uint32_t dst, const void* src) {
    asm volatile("cp.async.cg.shared.global [%0], [%1], 16;" :: "r"(dst), "l"(src));
}
#define CP_COMMIT() asm volatile("cp.async.commit_group;" ::: "memory")
#define CP_WAIT(n)  asm volatile("cp.async.wait_group %0;" :: "n"(n) : "memory")

__device__ __forceinline__ void ldsm_x4(uint32_t tbase, int row0, int kbyte,
                                        int lane, uint32_t r[4]) {
    int sub = lane >> 3, rr = lane & 7;
    uint32_t off = (uint32_t)((row0 + ((sub & 1) << 3) + rr) * 128
                              + kbyte + ((sub >> 1) << 4));
    off ^= (off >> 3) & 0x70;   // SW128
    asm volatile("ldmatrix.sync.aligned.m8n8.x4.shared.b16 {%0,%1,%2,%3}, [%4];"
        : "=r"(r[0]), "=r"(r[1]), "=r"(r[2]), "=r"(r[3]) : "r"(tbase + off));
}

__device__ __forceinline__ void mma16816(float* c, const uint32_t* a,
                                         uint32_t b0, uint32_t b1) {
    asm volatile("mma.sync.aligned.m16n8k16.row.col.f32.bf16.bf16.f32 "
        "{%0,%1,%2,%3}, {%4,%5,%6,%7}, {%8,%9}, {%0,%1,%2,%3};"
        : "+f"(c[0]), "+f"(c[1]), "+f"(c[2]), "+f"(c[3])
        : "r"(a[0]), "r"(a[1]), "r"(a[2]), "r"(a[3]), "r"(b0), "r"(b1));
}

// ---------------------------------------------------------------------------
// Kernel 1: crop_and_resize (TF semantics, 14x14) + 2x2 maxpool -> bf16 hi/lo
// ---------------------------------------------------------------------------
__global__ void roi_kernel(const float* __restrict__ feats,
                           const float* __restrict__ boxes, int N,
                           __nv_bfloat16* __restrict__ out_hi,
                           __nv_bfloat16* __restrict__ out_lo)
{
    int roi = blockIdx.x;
    if (roi >= N) return;
    __shared__ int   sy0[14], sy1[14], sx0[14], sx1[14];
    __shared__ float swy[14], swx[14];
    int t = threadIdx.x;
    if (t < 14) {
        float y1 = boxes[roi * 4 + 0];
        float x1 = boxes[roi * 4 + 1];
        float y2 = boxes[roi * 4 + 2];
        float x2 = boxes[roi * 4 + 3];
        float ys = y1 * 37.0f + (float)t * ((y2 - y1) * 37.0f / 13.0f);
        float xs = x1 * 49.0f + (float)t * ((x2 - x1) * 49.0f / 13.0f);
        float y0f = floorf(ys), x0f = floorf(xs);
        swy[t] = ys - y0f;
        swx[t] = xs - x0f;
        int y0 = min(max((int)y0f, 0), 37);
        int x0 = min(max((int)x0f, 0), 49);
        sy0[t] = y0; sy1[t] = min(y0 + 1, 37);
        sx0[t] = x0; sx1[t] = min(x0 + 1, 49);
    }
    __syncthreads();

    size_t rbase = (size_t)roi * DFLAT;
    for (int idx = t; idx < 7 * 7 * 128; idx += blockDim.x) {
        int c4 = idx & 127;
        int p  = idx >> 7;
        int pr = p / 7, pc = p % 7;
        int c  = c4 * 4;
        float4 best = make_float4(-1e30f, -1e30f, -1e30f, -1e30f);
#pragma unroll
        for (int dy = 0; dy < 2; dy++) {
            int iy = 2 * pr + dy;
            int ay = sy0[iy], by = sy1[iy];
            float fy = swy[iy];
#pragma unroll
            for (int dx = 0; dx < 2; dx++) {
                int ix = 2 * pc + dx;
                int ax = sx0[ix], bx = sx1[ix];
                float fx = swx[ix];
                float4 v00 = *(const float4*)(feats + ((ay * 50 + ax) * 512 + c));
                float4 v01 = *(const float4*)(feats + ((ay * 50 + bx) * 512 + c));
                float4 v10 = *(const float4*)(feats + ((by * 50 + ax) * 512 + c));
                float4 v11 = *(const float4*)(feats + ((by * 50 + bx) * 512 + c));
                float4 top, bot, val;
                top.x = v00.x + fx * (v01.x - v00.x);
                top.y = v00.y + fx * (v01.y - v00.y);
                top.z = v00.z + fx * (v01.z - v00.z);
                top.w = v00.w + fx * (v01.w - v00.w);
                bot.x = v10.x + fx * (v11.x - v10.x);
                bot.y = v10.y + fx * (v11.y - v10.y);
                bot.z = v10.z + fx * (v11.z - v10.z);
                bot.w = v10.w + fx * (v11.w - v10.w);
                val.x = top.x + fy * (bot.x - top.x);
                val.y = top.y + fy * (bot.y - top.y);
                val.z = top.z + fy * (bot.z - top.z);
                val.w = top.w + fy * (bot.w - top.w);
                best.x = fmaxf(best.x, val.x);
                best.y = fmaxf(best.y, val.y);
                best.z = fmaxf(best.z, val.z);
                best.w = fmaxf(best.w, val.w);
            }
        }
        size_t o = rbase + (size_t)p * 512 + c;
        uint2 hv, lv;
        hv.x = pack_bf(best.x, best.y);
        hv.y = pack_bf(best.z, best.w);
        lv.x = pack_bf(bfres(best.x), bfres(best.y));
        lv.y = pack_bf(bfres(best.z), bfres(best.w));
        *(uint2*)(out_hi + o) = hv;
        *(uint2*)(out_lo + o) = lv;
    }
}

// ---------------------------------------------------------------------------
// Kernel 2: transpose fp32 [K,N] -> bf16 hi/lo [N,K], packed 4B stores.
// Tile: 64 K x 32 N. Requires K%64==0, N%32==0.
// ---------------------------------------------------------------------------
__global__ void transpose_split(const float* __restrict__ W,
                                __nv_bfloat16* __restrict__ hi,
                                __nv_bfloat16* __restrict__ lo, int K, int N)
{
    __shared__ float tile[64][33];
    int kb = blockIdx.y * 64, nb = blockIdx.x * 32;
    int tx = threadIdx.x, ty = threadIdx.y;   // 32 x 8
    for (int i = ty; i < 64; i += 8)
        tile[i][tx] = W[(size_t)(kb + i) * N + nb + tx];
    __syncthreads();
    for (int i = ty; i < 32; i += 8) {        // i = n index within tile
        float v0 = tile[2 * tx][i];
        float v1 = tile[2 * tx + 1][i];
        size_t o = (size_t)(nb + i) * K + kb + 2 * tx;
        *(uint32_t*)(hi + o) = pack_bf(v0, v1);
        *(uint32_t*)(lo + o) = pack_bf(bfres(v0), bfres(v1));
    }
}

// ---------------------------------------------------------------------------
// Kernel 3: mma.sync split-bf16 GEMM.  C[M,4096] = relu(A[M,K] @ B^T + bias)
// CTA tile 128x128, BK=64, 8 warps (4Mx2N), warp tile 32x64.
// 3-stage cp.async pipeline, SW128 swizzle, ldmatrix + mma.m16n8k16.
// Term-major MMA issue: all fragments loaded first, then 3 groups of 16
// independent MMAs (Ah*Bh, Al*Bh, Ah*Bl) -> same-acc reuse distance = 16.
// ---------------------------------------------------------------------------
#define GBM 128
#define GBN 128
#define GKC 64                  // bf16 elems per stage (128 bytes/row)
#define TILE_B 16384            // 128 rows * 128B
#define STG_B  (4 * TILE_B)     // Ah, Al, Bh, Bl
#define NSTAGE 3
#define GEMM_SMEM (NSTAGE * STG_B + 1024)

__global__ void __launch_bounds__(256, 1)
gemm_split(const __nv_bfloat16* __restrict__ Ahi, const __nv_bfloat16* __restrict__ Alo,
           const __nv_bfloat16* __restrict__ Bhi, const __nv_bfloat16* __restrict__ Blo,
           const float* __restrict__ bias,
           __nv_bfloat16* __restrict__ outHi, __nv_bfloat16* __restrict__ outLo,
           float* __restrict__ outF,
           int M, int K, int mode)
{
    extern __shared__ char dsm_raw[];
    char* dsm = (char*)(((uintptr_t)dsm_raw + 1023) & ~(uintptr_t)1023);
    uint32_t sbase = smem_u32(dsm);

    int tid = threadIdx.x;
    int wid = tid >> 5, lane = tid & 31;
    int bm = blockIdx.x * GBM, bn = blockIdx.y * GBN;
    int wm = (wid >> 1) * 32, wn = (wid & 1) * 64;

    const __nv_bfloat16* gp[4];
    gp[0] = Ahi + (size_t)bm * K;
    gp[1] = Alo + (size_t)bm * K;
    gp[2] = Bhi + (size_t)bn * K;
    gp[3] = Blo + (size_t)bn * K;

    const int S = K / GKC;

    auto load_stage = [&](int s) {
        int kbyte0 = s * (GKC * 2);
        uint32_t sb = sbase + (uint32_t)(s % NSTAGE) * STG_B;
#pragma unroll
        for (int i = 0; i < 16; i++) {
            int idx  = tid + i * 256;
            int tile = idx >> 10;
            int row  = (idx >> 3) & 127;
            int c    = idx & 7;
            const char* src = (const char*)(gp[tile] + (size_t)row * K)
                            + kbyte0 + c * 16;
            uint32_t off = (uint32_t)(row * 128 + c * 16);
            off ^= (off >> 3) & 0x70;
            cp16(sb + (uint32_t)tile * TILE_B + off, src);
        }
        CP_COMMIT();
    };

    float acc[2][8][4];
#pragma unroll
    for (int mi = 0; mi < 2; mi++)
#pragma unroll
        for (int ni = 0; ni < 8; ni++)
#pragma unroll
            for (int j = 0; j < 4; j++) acc[mi][ni][j] = 0.0f;

    load_stage(0);
    load_stage(1);

    for (int s = 0; s < S; s++) {
        if (s + 2 < S) load_stage(s + 2);
        if (s + 2 < S)      { CP_WAIT(2); }
        else if (s + 1 < S) { CP_WAIT(1); }
        else                { CP_WAIT(0); }
        __syncthreads();

        uint32_t sb  = sbase + (uint32_t)(s % NSTAGE) * STG_B;
        uint32_t tAh = sb, tAl = sb + TILE_B;
        uint32_t tBh = sb + 2 * TILE_B, tBl = sb + 3 * TILE_B;

#pragma unroll
        for (int ks = 0; ks < 4; ks++) {
            int kb = ks * 32;   // 16 bf16 = 32 bytes

            // ---- load ALL fragments for this k-slice up front ----
            uint32_t a[2][2][4];          // [hi/lo][mi]
#pragma unroll
            for (int mi = 0; mi < 2; mi++) {
                ldsm_x4(tAh, wm + mi * 16, kb, lane, a[0][mi]);
                ldsm_x4(tAl, wm + mi * 16, kb, lane, a[1][mi]);
            }
            uint32_t bh[4][4], bl[4][4];
#pragma unroll
            for (int g = 0; g < 4; g++) ldsm_x4(tBh, wn + g * 16, kb, lane, bh[g]);
#pragma unroll
            for (int g = 0; g < 4; g++) ldsm_x4(tBl, wn + g * 16, kb, lane, bl[g]);

            // ---- group 1: Ah * Bh (16 independent MMAs) ----
#pragma unroll
            for (int mi = 0; mi < 2; mi++)
#pragma unroll
                for (int g = 0; g < 4; g++) {
                    mma16816(acc[mi][2 * g],     a[0][mi], bh[g][0], bh[g][2]);
                    mma16816(acc[mi][2 * g + 1], a[0][mi], bh[g][1], bh[g][3]);
                }
            // ---- group 2: Al * Bh ----
#pragma unroll
            for (int mi = 0; mi < 2; mi++)
#pragma unroll
                for (int g = 0; g < 4; g++) {
                    mma16816(acc[mi][2 * g],     a[1][mi], bh[g][0], bh[g][2]);
                    mma16816(acc[mi][2 * g + 1], a[1][mi], bh[g][1], bh[g][3]);
                }
            // ---- group 3: Ah * Bl ----
#pragma unroll
            for (int mi = 0; mi < 2; mi++)
#pragma unroll
                for (int g = 0; g < 4; g++) {
                    mma16816(acc[mi][2 * g],     a[0][mi], bl[g][0], bl[g][2]);
                    mma16816(acc[mi][2 * g + 1], a[0][mi], bl[g][1], bl[g][3]);
                }
        }
        __syncthreads();
    }

    // ---- epilogue ----
    int lq = lane >> 2, lr = lane & 3;
#pragma unroll
    for (int mi = 0; mi < 2; mi++) {
#pragma unroll
        for (int half = 0; half < 2; half++) {
            int m = bm + wm + mi * 16 + lq + half * 8;
            if (m >= M) continue;
#pragma unroll
            for (int ni = 0; ni < 8; ni++) {
                int n = bn + wn + ni * 8 + lr * 2;
                float2 bv = *(const float2*)(bias + n);
                float v0 = fmaxf(acc[mi][ni][2 * half]     + bv.x, 0.0f);
                float v1 = fmaxf(acc[mi][ni][2 * half + 1] + bv.y, 0.0f);
                if (mode == 0) {
                    *(uint32_t*)(outHi + (size_t)m * HID + n) = pack_bf(v0, v1);
                    *(uint32_t*)(outLo + (size_t)m * HID + n) =
                        pack_bf(bfres(v0), bfres(v1));
                } else {
                    float2 ov = make_float2(v0, v1);
                    *(float2*)(outF + (size_t)m * HID + n) = ov;
                }
            }
        }
    }
}

// ---------------------------------------------------------------------------
// Kernel 4: head weight transpose (tiny)
// ---------------------------------------------------------------------------
__global__ void wt_kernel(const float* __restrict__ Wc, const float* __restrict__ Wr)
{
    for (int idx = blockIdx.x * blockDim.x + threadIdx.x; idx < NHEAD * HID;
         idx += gridDim.x * blockDim.x) {
        int j = idx >> 12;
        int k = idx & 4095;
        g_WT[idx] = (j < 21) ? Wc[k * 21 + j] : Wr[k * 80 + (j - 21)];
    }
}

// ---------------------------------------------------------------------------
// Kernel 5: heads + softmax
// ---------------------------------------------------------------------------
#define RPB 2
__global__ void __launch_bounds__(256)
head_kernel(const float* __restrict__ bc, const float* __restrict__ br,
            float* __restrict__ out, int N)
{
    __shared__ float xs[RPB][HID];
    __shared__ float lg[RPB][NHEAD];
    int roi0 = blockIdx.x * RPB;
    int t = threadIdx.x;

    for (int r = 0; r < RPB; r++) {
        int roi = roi0 + r;
        if (roi < N) {
            const float4* src = (const float4*)(g_h2 + (size_t)roi * HID);
            for (int i = t; i < HID / 4; i += 256) ((float4*)xs[r])[i] = src[i];
        } else {
            for (int i = t; i < HID / 4; i += 256)
                ((float4*)xs[r])[i] = make_float4(0.f, 0.f, 0.f, 0.f);
        }
    }
    __syncthreads();

    int w = t >> 5, lane = t & 31;
    for (int j = w; j < NHEAD; j += 8) {
        const float4* wp = (const float4*)(g_WT + (size_t)j * HID);
        float acc0 = 0.f, acc1 = 0.f;
        for (int i = lane; i < HID / 4; i += 32) {
            float4 wv = wp[i];
            float4 a = ((float4*)xs[0])[i];
            float4 b = ((float4*)xs[1])[i];
            acc0 += wv.x * a.x + wv.y * a.y + wv.z * a.z + wv.w * a.w;
            acc1 += wv.x * b.x + wv.y * b.y + wv.z * b.z + wv.w * b.w;
        }
#pragma unroll
        for (int o = 16; o; o >>= 1) {
            acc0 += __shfl_down_sync(0xffffffffu, acc0, o);
            acc1 += __shfl_down_sync(0xffffffffu, acc1, o);
        }
        if (lane == 0) {
            float bias = (j < 21) ? bc[j] : br[j - 21];
            lg[0][j] = acc0 + bias;
            lg[1][j] = acc1 + bias;
        }
    }
    __syncthreads();

    if (t < RPB) {
        int roi = roi0 + t;
        if (roi < N) {
            float mx = -1e30f;
            for (int j = 0; j < 21; j++) mx = fmaxf(mx, lg[t][j]);
            float s = 0.f;
            float e[21];
            for (int j = 0; j < 21; j++) { e[j] = expf(lg[t][j] - mx); s += e[j]; }
            float inv = 1.0f / s;
            for (int j = 0; j < 21; j++) out[(size_t)roi * 21 + j] = e[j] * inv;
        }
    }
    for (int idx = t; idx < RPB * 80; idx += 256) {
        int r = idx / 80, j = idx % 80;
        int roi = roi0 + r;
        if (roi < N) out[(size_t)N * 21 + (size_t)roi * 80 + j] = lg[r][21 + j];
    }
}

// ---------------------------------------------------------------------------
extern "C" void kernel_launch(void* const* d_in, const int* in_sizes, int n_in,
                              void* d_out, int out_size)
{
    const float* feats = (const float*)d_in[0];
    const float* props = (const float*)d_in[1];
    const float* W1    = (const float*)d_in[2];
    const float* b1    = (const float*)d_in[3];
    const float* W2    = (const float*)d_in[4];
    const float* b2    = (const float*)d_in[5];
    const float* Wc    = (const float*)d_in[6];
    const float* bc    = (const float*)d_in[7];
    const float* Wr    = (const float*)d_in[8];
    const float* br    = (const float*)d_in[9];
    float* out = (float*)d_out;

    int N = in_sizes[1] / 4;
    if (N > 1000) N = 1000;

    __nv_bfloat16 *phi, *plo, *w1h, *w1l, *w2h, *w2l, *h1h, *h1l;
    cudaGetSymbolAddress((void**)&phi, g_pool_hi);
    cudaGetSymbolAddress((void**)&plo, g_pool_lo);
    cudaGetSymbolAddress((void**)&w1h, g_W1T_hi);
    cudaGetSymbolAddress((void**)&w1l, g_W1T_lo);
    cudaGetSymbolAddress((void**)&w2h, g_W2T_hi);
    cudaGetSymbolAddress((void**)&w2l, g_W2T_lo);
    cudaGetSymbolAddress((void**)&h1h, g_h1_hi);
    cudaGetSymbolAddress((void**)&h1l, g_h1_lo);
    float* h2;
    cudaGetSymbolAddress((void**)&h2, g_h2);

    cudaFuncSetAttribute(gemm_split,
                         cudaFuncAttributeMaxDynamicSharedMemorySize, GEMM_SMEM);

    // weight prep (64K x 32N tiles, packed stores)
    transpose_split<<<dim3(HID / 32, DFLAT / 64), dim3(32, 8)>>>(W1, w1h, w1l, DFLAT, HID);
    transpose_split<<<dim3(HID / 32, HID / 64),  dim3(32, 8)>>>(W2, w2h, w2l, HID, HID);
    wt_kernel<<<256, 256>>>(Wc, Wr);

    // ROI pooling -> bf16 hi/lo
    roi_kernel<<<N, 256>>>(feats, props, N, phi, plo);

    int MT = (N + GBM - 1) / GBM;
    dim3 grid(MT, HID / GBN);
    gemm_split<<<grid, 256, GEMM_SMEM>>>(phi, plo, w1h, w1l, b1,
                                         h1h, h1l, nullptr, N, DFLAT, 0);
    gemm_split<<<grid, 256, GEMM_SMEM>>>(h1h, h1l, w2h, w2l, b2,
                                         nullptr, nullptr, h2, N, HID, 1);

    head_kernel<<<(N + RPB - 1) / RPB, 256>>>(bc, br, out, N);
}